// round 4
// baseline (speedup 1.0000x reference)
#include <cuda_runtime.h>
#include <cstddef>

#define DIM    1024
#define HEADS  16
#define DEPTH  64
#define BATCH  4
#define SEQ    2048
#define ROWS   (BATCH * SEQ)   // 8192

// ---------------- scratch (device globals; no allocation allowed) ----------
__device__ float g_Qh[(size_t)BATCH * HEADS * SEQ * DEPTH];  // [B,H,S,D] tf32-rounded
__device__ float g_Kh[(size_t)BATCH * HEADS * SEQ * DEPTH];
__device__ float g_Vh[(size_t)BATCH * HEADS * SEQ * DEPTH];
__device__ float g_Att[(size_t)ROWS * DIM];                  // [B,S,DIM]

// ---------------- tf32 / async helpers ------------------------------------
__device__ __forceinline__ unsigned f2tf(float x) {
    unsigned u;
    asm("cvt.rna.tf32.f32 %0, %1;" : "=r"(u) : "f"(x));
    return u;
}
__device__ __forceinline__ float tf(float x) { return __uint_as_float(f2tf(x)); }

__device__ __forceinline__ void cp16(void* dst, const void* src) {
    unsigned d = (unsigned)__cvta_generic_to_shared(dst);
    asm volatile("cp.async.cg.shared.global [%0], [%1], 16;" :: "r"(d), "l"(src));
}
__device__ __forceinline__ void cp_commit() {
    asm volatile("cp.async.commit_group;");
}

// D += A(16x8) * B(8x8), tf32, row.col
__device__ __forceinline__ void mma8(float* d, const unsigned* a, const unsigned* b) {
    asm volatile(
        "mma.sync.aligned.m16n8k8.row.col.f32.tf32.tf32.f32 "
        "{%0,%1,%2,%3},{%4,%5,%6,%7},{%8,%9},{%0,%1,%2,%3};"
        : "+f"(d[0]), "+f"(d[1]), "+f"(d[2]), "+f"(d[3])
        : "r"(a[0]), "r"(a[1]), "r"(a[2]), "r"(a[3]), "r"(b[0]), "r"(b[1]));
}

// ---------------------------------------------------------------------------
// TF32 GEMM, 3-stage cp.async pipeline. C = A[M,1024] @ B[1024,1024].
// Block 128x128, 128 threads = 4 warps (2x2), warp tile 64x64, k-step 16.
// mode 0: C flat. mode 1: C scattered to [B,H,S,D], tf32-rounded.
// ---------------------------------------------------------------------------
#define AST 20
#define BST 140
#define G_AS (128 * AST)          // 2560 floats / stage
#define G_BS (16 * BST)           // 2240 floats / stage
#define GEMM_SMEM_FLOATS (3 * (G_AS + G_BS))
#define GEMM_SMEM_BYTES  (GEMM_SMEM_FLOATS * 4)

__global__ void __launch_bounds__(128, 2) gemm_tf32(
    const float* __restrict__ A, const float* __restrict__ B,
    float* __restrict__ C, int mode)
{
    extern __shared__ float gsm[];

    const int tid = threadIdx.x, lane = tid & 31, w = tid >> 5;
    const int g = lane >> 2, tg = lane & 3;
    const int wm = (w & 1) << 6;
    const int wn = (w >> 1) << 6;
    const int m0 = blockIdx.y << 7;
    const int n0 = blockIdx.x << 7;

    const int ar = tid >> 2;          // 0..31
    const int ac = (tid & 3) << 2;    // 0,4,8,12
    const int br = tid >> 5;          // 0..3
    const int bc = lane << 2;         // 0..124

    float acc[4][8][4];
#pragma unroll
    for (int i = 0; i < 4; i++)
#pragma unroll
        for (int j = 0; j < 8; j++)
#pragma unroll
            for (int c = 0; c < 4; c++) acc[i][j][c] = 0.f;

    // stage copy: k-offset kk into stage st
    auto stage_copy = [&](int st, int kk) {
        float* as = gsm + st * (G_AS + G_BS);
        float* bs = as + G_AS;
#pragma unroll
        for (int j = 0; j < 4; j++) {
            cp16(&as[(ar + 32 * j) * AST + ac],
                 A + (size_t)(m0 + ar + 32 * j) * DIM + kk + ac);
            cp16(&bs[(br + 4 * j) * BST + bc],
                 B + (size_t)(kk + br + 4 * j) * DIM + n0 + bc);
        }
        cp_commit();
    };

    stage_copy(0, 0);
    stage_copy(1, 16);
    stage_copy(2, 32);

    const int NIT = DIM / 16;   // 64
    for (int i = 0; i < NIT; i++) {
        asm volatile("cp.async.wait_group 2;");
        __syncthreads();

        int st = i % 3;
        const float* as = gsm + st * (G_AS + G_BS);
        const float* bs = as + G_AS;

#pragma unroll
        for (int k0 = 0; k0 < 16; k0 += 8) {
            unsigned af[4][4];
#pragma unroll
            for (int mf = 0; mf < 4; mf++) {
                int m = wm + (mf << 4);
                af[mf][0] = f2tf(as[(m + g) * AST + k0 + tg]);
                af[mf][1] = f2tf(as[(m + g + 8) * AST + k0 + tg]);
                af[mf][2] = f2tf(as[(m + g) * AST + k0 + tg + 4]);
                af[mf][3] = f2tf(as[(m + g + 8) * AST + k0 + tg + 4]);
            }
#pragma unroll
            for (int nf = 0; nf < 8; nf++) {
                unsigned bf[2];
                int n = wn + (nf << 3) + g;
                bf[0] = f2tf(bs[(k0 + tg) * BST + n]);
                bf[1] = f2tf(bs[(k0 + tg + 4) * BST + n]);
#pragma unroll
                for (int mf = 0; mf < 4; mf++)
                    mma8(acc[mf][nf], af[mf], bf);
            }
        }
        __syncthreads();

        if (i + 3 < NIT) stage_copy(st, (i + 3) * 16);
        else             cp_commit();   // keep group accounting aligned
    }

    // epilogue
#pragma unroll
    for (int mf = 0; mf < 4; mf++) {
        int r0 = m0 + wm + (mf << 4) + g;
#pragma unroll
        for (int nf = 0; nf < 8; nf++) {
            int c = n0 + wn + (nf << 3) + (tg << 1);
            if (mode == 0) {
                *(float2*)&C[(size_t)r0 * DIM + c] =
                    make_float2(acc[mf][nf][0], acc[mf][nf][1]);
                *(float2*)&C[(size_t)(r0 + 8) * DIM + c] =
                    make_float2(acc[mf][nf][2], acc[mf][nf][3]);
            } else {
                int h = c >> 6, d = c & 63;
                int bb0 = r0 >> 11, s0 = r0 & 2047;
                int bb1 = (r0 + 8) >> 11, s1 = (r0 + 8) & 2047;
                size_t i0 = (((size_t)(bb0 * HEADS + h) * SEQ + s0) << 6) + d;
                size_t i1 = (((size_t)(bb1 * HEADS + h) * SEQ + s1) << 6) + d;
                *(float2*)&C[i0] = make_float2(tf(acc[mf][nf][0]), tf(acc[mf][nf][1]));
                *(float2*)&C[i1] = make_float2(tf(acc[mf][nf][2]), tf(acc[mf][nf][3]));
            }
        }
    }
}

// ---------------------------------------------------------------------------
// Flash attention, TF32 tensor cores, cp.async double-buffered K/V.
// Block = (b, h, 128-query tile), 128 threads = 4 warps, 32 q rows/warp.
// Q fragments held in registers (inputs pre-rounded to tf32 by projections).
// smem: buf0/buf1 [128][68] (K rows 0-63 | V rows 64-127; P aliases current),
//       Vt [64][68], Msk[2048] premultiplied by 1e9.
// ---------------------------------------------------------------------------
#define FST 68
#define FB_FLOATS (128 * FST)
#define FA_SMEM_FLOATS (2 * FB_FLOATS + 64 * FST + SEQ)
#define FA_SMEM_BYTES  (FA_SMEM_FLOATS * 4)

__global__ void __launch_bounds__(128, 2) flash_tf32(
    const float* __restrict__ Qh, const float* __restrict__ Kh,
    const float* __restrict__ Vh, const float* __restrict__ Mask,
    float* __restrict__ Att)
{
    extern __shared__ float smf[];
    float* buf0 = smf;
    float* buf1 = smf + FB_FLOATS;
    float* Vt   = smf + 2 * FB_FLOATS;       // [d][j]
    float* Msk  = Vt + 64 * FST;             // [2048]

    const int tid = threadIdx.x, lane = tid & 31, w = tid >> 5;
    const int g = lane >> 2, tg = lane & 3;
    const int q0 = w << 5;
    const int b = blockIdx.z, h = blockIdx.y, qt = blockIdx.x;

    const float* Qg = Qh + ((size_t)(b * HEADS + h) * SEQ + qt * 128) * DEPTH;
    const float* Kg = Kh + (size_t)(b * HEADS + h) * SEQ * DEPTH;
    const float* Vg = Vh + (size_t)(b * HEADS + h) * SEQ * DEPTH;
    const float* Mg = Mask + (size_t)b * SEQ;

    // K/V tile copy for key-tile kt into buffer bsel
    auto copy_kv = [&](int bsel, int kt) {
        float* buf = bsel ? buf1 : buf0;
        const float* Kgt = Kg + kt * 64 * DEPTH;
        const float* Vgt = Vg + kt * 64 * DEPTH;
#pragma unroll
        for (int it = 0; it < 8; it++) {
            int idx = tid + it * 128;
            int r = idx >> 4, c = (idx & 15) << 2;
            cp16(&buf[r * FST + c],        Kgt + r * DEPTH + c);
            cp16(&buf[(64 + r) * FST + c], Vgt + r * DEPTH + c);
        }
        cp_commit();
    };

    copy_kv(0, 0);   // prologue: first K/V tile in flight

    // mask -> smem, premultiplied by 1e9 (whole sequence, once)
#pragma unroll
    for (int it = 0; it < 4; it++) {
        int idx = (tid + it * 128) << 2;
        float4 mv = *(const float4*)(Mg + idx);
        *(float4*)&Msk[idx] = make_float4(mv.x * 1e9f, mv.y * 1e9f,
                                          mv.z * 1e9f, mv.w * 1e9f);
    }

    // Q fragments -> registers (pre-rounded tf32; x0.125 is exact)
    unsigned qa[8][2][4];
#pragma unroll
    for (int k0 = 0; k0 < 8; k0++)
#pragma unroll
        for (int mf = 0; mf < 2; mf++) {
            int m = q0 + (mf << 4);
            qa[k0][mf][0] = __float_as_uint(0.125f * Qg[(m + g) * DEPTH + (k0 << 3) + tg]);
            qa[k0][mf][1] = __float_as_uint(0.125f * Qg[(m + g + 8) * DEPTH + (k0 << 3) + tg]);
            qa[k0][mf][2] = __float_as_uint(0.125f * Qg[(m + g) * DEPTH + (k0 << 3) + tg + 4]);
            qa[k0][mf][3] = __float_as_uint(0.125f * Qg[(m + g + 8) * DEPTH + (k0 << 3) + tg + 4]);
        }

    float o[2][8][4];
#pragma unroll
    for (int mf = 0; mf < 2; mf++)
#pragma unroll
        for (int nf = 0; nf < 8; nf++)
#pragma unroll
            for (int c = 0; c < 4; c++) o[mf][nf][c] = 0.f;
    float mrow[4] = {-1e30f, -1e30f, -1e30f, -1e30f};
    float lrow[4] = {0.f, 0.f, 0.f, 0.f};

    __syncthreads();   // mask staged (buffers not yet read)

    for (int kt = 0; kt < SEQ / 64; kt++) {
        asm volatile("cp.async.wait_group 0;");
        __syncthreads();                       // (B) tile kt ready; prev P reads done

        float* cur = (kt & 1) ? buf1 : buf0;
        float* Ksm = cur;                      // rows 0-63
        float* Vsm = cur + 64 * FST;           // rows 64-127
        float* Ps  = cur;                      // aliased after (C)

        if (kt + 1 < SEQ / 64) copy_kv((kt + 1) & 1, kt + 1);

        // transpose V -> Vt[d][j]
        {
            int dd = tid & 63;
            int j0 = (tid >> 6) << 5;
#pragma unroll
            for (int jj = 0; jj < 32; jj += 4) {
                float4 t;
                t.x = Vsm[(j0 + jj + 0) * FST + dd];
                t.y = Vsm[(j0 + jj + 1) * FST + dd];
                t.z = Vsm[(j0 + jj + 2) * FST + dd];
                t.w = Vsm[(j0 + jj + 3) * FST + dd];
                *(float4*)&Vt[dd * FST + j0 + jj] = t;
            }
        }

        // S = Q @ K^T
        float s[2][8][4];
#pragma unroll
        for (int mf = 0; mf < 2; mf++)
#pragma unroll
            for (int nf = 0; nf < 8; nf++)
#pragma unroll
                for (int c = 0; c < 4; c++) s[mf][nf][c] = 0.f;

#pragma unroll
        for (int k0 = 0; k0 < 8; k0++) {
#pragma unroll
            for (int nf = 0; nf < 8; nf++) {
                unsigned bf[2];
                bf[0] = __float_as_uint(Ksm[((nf << 3) + g) * FST + (k0 << 3) + tg]);
                bf[1] = __float_as_uint(Ksm[((nf << 3) + g) * FST + (k0 << 3) + tg + 4]);
                mma8(s[0][nf], qa[k0][0], bf);
                mma8(s[1][nf], qa[k0][1], bf);
            }
        }

        // mask + online softmax
        const float* Mk = Msk + kt * 64;
        float mx[4] = {-1e30f, -1e30f, -1e30f, -1e30f};
#pragma unroll
        for (int mf = 0; mf < 2; mf++)
#pragma unroll
            for (int nf = 0; nf < 8; nf++) {
                float k0v = Mk[(nf << 3) + (tg << 1)];
                float k1v = Mk[(nf << 3) + (tg << 1) + 1];
                s[mf][nf][0] -= k0v; s[mf][nf][1] -= k1v;
                s[mf][nf][2] -= k0v; s[mf][nf][3] -= k1v;
                mx[mf * 2 + 0] = fmaxf(mx[mf * 2 + 0], fmaxf(s[mf][nf][0], s[mf][nf][1]));
                mx[mf * 2 + 1] = fmaxf(mx[mf * 2 + 1], fmaxf(s[mf][nf][2], s[mf][nf][3]));
            }
#pragma unroll
        for (int r = 0; r < 4; r++) {
            mx[r] = fmaxf(mx[r], __shfl_xor_sync(0xffffffffu, mx[r], 1));
            mx[r] = fmaxf(mx[r], __shfl_xor_sync(0xffffffffu, mx[r], 2));
        }
        float al[4];
#pragma unroll
        for (int r = 0; r < 4; r++) {
            float mn = fmaxf(mrow[r], mx[r]);
            al[r] = __expf(mrow[r] - mn);
            mrow[r] = mn;
        }
        float sm[4] = {0.f, 0.f, 0.f, 0.f};
#pragma unroll
        for (int mf = 0; mf < 2; mf++)
#pragma unroll
            for (int nf = 0; nf < 8; nf++) {
                s[mf][nf][0] = __expf(s[mf][nf][0] - mrow[mf * 2 + 0]);
                s[mf][nf][1] = __expf(s[mf][nf][1] - mrow[mf * 2 + 0]);
                s[mf][nf][2] = __expf(s[mf][nf][2] - mrow[mf * 2 + 1]);
                s[mf][nf][3] = __expf(s[mf][nf][3] - mrow[mf * 2 + 1]);
                sm[mf * 2 + 0] += s[mf][nf][0] + s[mf][nf][1];
                sm[mf * 2 + 1] += s[mf][nf][2] + s[mf][nf][3];
            }
#pragma unroll
        for (int r = 0; r < 4; r++) {
            sm[r] += __shfl_xor_sync(0xffffffffu, sm[r], 1);
            sm[r] += __shfl_xor_sync(0xffffffffu, sm[r], 2);
            lrow[r] = lrow[r] * al[r] + sm[r];
        }
#pragma unroll
        for (int mf = 0; mf < 2; mf++)
#pragma unroll
            for (int nf = 0; nf < 8; nf++) {
                o[mf][nf][0] *= al[mf * 2 + 0]; o[mf][nf][1] *= al[mf * 2 + 0];
                o[mf][nf][2] *= al[mf * 2 + 1]; o[mf][nf][3] *= al[mf * 2 + 1];
            }

        __syncthreads();   // (C) all QK reads + Vt writes done; K/V region -> P

        // P -> smem (warp-private rows)
#pragma unroll
        for (int mf = 0; mf < 2; mf++) {
            int m = q0 + (mf << 4);
#pragma unroll
            for (int nf = 0; nf < 8; nf++) {
                *(float2*)&Ps[(m + g) * FST + (nf << 3) + (tg << 1)] =
                    make_float2(s[mf][nf][0], s[mf][nf][1]);
                *(float2*)&Ps[(m + g + 8) * FST + (nf << 3) + (tg << 1)] =
                    make_float2(s[mf][nf][2], s[mf][nf][3]);
            }
        }
        __syncwarp();

        // O += P @ V
#pragma unroll
        for (int j0 = 0; j0 < 8; j0++) {
            unsigned pa[2][4];
#pragma unroll
            for (int mf = 0; mf < 2; mf++) {
                int m = q0 + (mf << 4);
                pa[mf][0] = __float_as_uint(Ps[(m + g) * FST + (j0 << 3) + tg]);
                pa[mf][1] = __float_as_uint(Ps[(m + g + 8) * FST + (j0 << 3) + tg]);
                pa[mf][2] = __float_as_uint(Ps[(m + g) * FST + (j0 << 3) + tg + 4]);
                pa[mf][3] = __float_as_uint(Ps[(m + g + 8) * FST + (j0 << 3) + tg + 4]);
            }
#pragma unroll
            for (int nf = 0; nf < 8; nf++) {
                unsigned bf[2];
                bf[0] = __float_as_uint(Vt[((nf << 3) + g) * FST + (j0 << 3) + tg]);
                bf[1] = __float_as_uint(Vt[((nf << 3) + g) * FST + (j0 << 3) + tg + 4]);
                mma8(o[0][nf], pa[0], bf);
                mma8(o[1][nf], pa[1], bf);
            }
        }
    }

    // normalize + write [B,S,DIM]
#pragma unroll
    for (int mf = 0; mf < 2; mf++) {
        float inv0 = 1.0f / lrow[mf * 2 + 0];
        float inv1 = 1.0f / lrow[mf * 2 + 1];
        int r0 = qt * 128 + q0 + (mf << 4) + g;
        int r1 = r0 + 8;
#pragma unroll
        for (int nf = 0; nf < 8; nf++) {
            int c = h * 64 + (nf << 3) + (tg << 1);
            *(float2*)&Att[(size_t)(b * SEQ + r0) * DIM + c] =
                make_float2(o[mf][nf][0] * inv0, o[mf][nf][1] * inv0);
            *(float2*)&Att[(size_t)(b * SEQ + r1) * DIM + c] =
                make_float2(o[mf][nf][2] * inv1, o[mf][nf][3] * inv1);
        }
    }
}

// ---------------------------------------------------------------------------
extern "C" void kernel_launch(void* const* d_in, const int* in_sizes, int n_in,
                              void* d_out, int out_size)
{
    const float* q    = (const float*)d_in[0];
    const float* k    = (const float*)d_in[1];
    const float* v    = (const float*)d_in[2];
    const float* mask = (const float*)d_in[3];
    const float* WQ   = (const float*)d_in[4];
    const float* WK   = (const float*)d_in[5];
    const float* WV   = (const float*)d_in[6];
    const float* WO   = (const float*)d_in[7];
    float* out = (float*)d_out;

    float *Qh, *Kh, *Vh, *Att;
    cudaGetSymbolAddress((void**)&Qh,  g_Qh);
    cudaGetSymbolAddress((void**)&Kh,  g_Kh);
    cudaGetSymbolAddress((void**)&Vh,  g_Vh);
    cudaGetSymbolAddress((void**)&Att, g_Att);

    cudaFuncSetAttribute(gemm_tf32,
                         cudaFuncAttributeMaxDynamicSharedMemorySize,
                         GEMM_SMEM_BYTES);
    cudaFuncSetAttribute(flash_tf32,
                         cudaFuncAttributeMaxDynamicSharedMemorySize,
                         FA_SMEM_BYTES);

    dim3 gg(DIM / 128, ROWS / 128);   // (8, 64)
    gemm_tf32<<<gg, 128, GEMM_SMEM_BYTES>>>(q, WQ, Qh, 1);
    gemm_tf32<<<gg, 128, GEMM_SMEM_BYTES>>>(k, WK, Kh, 1);
    gemm_tf32<<<gg, 128, GEMM_SMEM_BYTES>>>(v, WV, Vh, 1);
    flash_tf32<<<dim3(SEQ / 128, HEADS, BATCH), 128, FA_SMEM_BYTES>>>(
        Qh, Kh, Vh, mask, Att);
    gemm_tf32<<<gg, 128, GEMM_SMEM_BYTES>>>(Att, WO, out, 0);
}

// round 5
// speedup vs baseline: 1.0514x; 1.0514x over previous
#include <cuda_runtime.h>
#include <cstddef>

#define DIM    1024
#define HEADS  16
#define DEPTH  64
#define BATCH  4
#define SEQ    2048
#define ROWS   (BATCH * SEQ)   // 8192

// ---------------- scratch (device globals; no allocation allowed) ----------
__device__ float g_Qh[(size_t)BATCH * HEADS * SEQ * DEPTH];  // [B,H,S,D] tf32-rounded
__device__ float g_Kh[(size_t)BATCH * HEADS * SEQ * DEPTH];
__device__ float g_Vh[(size_t)BATCH * HEADS * SEQ * DEPTH];
__device__ float g_Att[(size_t)ROWS * DIM];                  // [B,S,DIM]

// ---------------- tf32 helpers --------------------------------------------
__device__ __forceinline__ unsigned f2tf(float x) {
    unsigned u;
    asm("cvt.rna.tf32.f32 %0, %1;" : "=r"(u) : "f"(x));
    return u;
}
__device__ __forceinline__ float tf(float x) { return __uint_as_float(f2tf(x)); }
__device__ __forceinline__ float4 tf4(float4 v) {
    return make_float4(tf(v.x), tf(v.y), tf(v.z), tf(v.w));
}

// D += A(16x8) * B(8x8), tf32, row.col
__device__ __forceinline__ void mma8(float* d, const unsigned* a, const unsigned* b) {
    asm volatile(
        "mma.sync.aligned.m16n8k8.row.col.f32.tf32.tf32.f32 "
        "{%0,%1,%2,%3},{%4,%5,%6,%7},{%8,%9},{%0,%1,%2,%3};"
        : "+f"(d[0]), "+f"(d[1]), "+f"(d[2]), "+f"(d[3])
        : "r"(a[0]), "r"(a[1]), "r"(a[2]), "r"(a[3]), "r"(b[0]), "r"(b[1]));
}

// ---------------------------------------------------------------------------
// TF32 GEMM body (R3-proven): C = A[M,1024] @ B[1024,1024].
// Block 128x128, 128 threads = 4 warps (2x2), warp tile 64x64, k-step 16,
// register-prefetch double buffering.
// MODE 0: C flat. MODE 1: C scattered to [B,H,S,D], tf32-rounded.
// ---------------------------------------------------------------------------
#define AST 20
#define BST 140

template <int MODE>
__device__ __forceinline__ void gemm_body(
    const float* __restrict__ A, const float* __restrict__ B,
    float* __restrict__ C, int m0, int n0)
{
    __shared__ float As[128 * AST];
    __shared__ float Bs[16 * BST];

    const int tid = threadIdx.x, lane = tid & 31, w = tid >> 5;
    const int g = lane >> 2, tg = lane & 3;
    const int wm = (w & 1) << 6;
    const int wn = (w >> 1) << 6;

    const int ar = tid >> 2;
    const int ac = (tid & 3) << 2;
    const int br = tid >> 5;
    const int bc = lane << 2;

    float acc[4][8][4];
#pragma unroll
    for (int i = 0; i < 4; i++)
#pragma unroll
        for (int j = 0; j < 8; j++)
#pragma unroll
            for (int c = 0; c < 4; c++) acc[i][j][c] = 0.f;

    float4 pa[4], pb[4];
#pragma unroll
    for (int j = 0; j < 4; j++) {
        pa[j] = *(const float4*)(A + (size_t)(m0 + ar + 32 * j) * DIM + ac);
        pb[j] = *(const float4*)(B + (size_t)(br + 4 * j) * DIM + n0 + bc);
    }

    for (int kk = 0; kk < DIM; kk += 16) {
#pragma unroll
        for (int j = 0; j < 4; j++) {
            *(float4*)&As[(ar + 32 * j) * AST + ac] = tf4(pa[j]);
            *(float4*)&Bs[(br + 4 * j) * BST + bc]  = tf4(pb[j]);
        }
        __syncthreads();

        if (kk + 16 < DIM) {
#pragma unroll
            for (int j = 0; j < 4; j++) {
                pa[j] = *(const float4*)(A + (size_t)(m0 + ar + 32 * j) * DIM + kk + 16 + ac);
                pb[j] = *(const float4*)(B + (size_t)(kk + 16 + br + 4 * j) * DIM + n0 + bc);
            }
        }

#pragma unroll
        for (int k0 = 0; k0 < 16; k0 += 8) {
            unsigned af[4][4];
#pragma unroll
            for (int mf = 0; mf < 4; mf++) {
                int m = wm + (mf << 4);
                af[mf][0] = __float_as_uint(As[(m + g) * AST + k0 + tg]);
                af[mf][1] = __float_as_uint(As[(m + g + 8) * AST + k0 + tg]);
                af[mf][2] = __float_as_uint(As[(m + g) * AST + k0 + tg + 4]);
                af[mf][3] = __float_as_uint(As[(m + g + 8) * AST + k0 + tg + 4]);
            }
#pragma unroll
            for (int nf = 0; nf < 8; nf++) {
                unsigned bf[2];
                int n = wn + (nf << 3) + g;
                bf[0] = __float_as_uint(Bs[(k0 + tg) * BST + n]);
                bf[1] = __float_as_uint(Bs[(k0 + tg + 4) * BST + n]);
#pragma unroll
                for (int mf = 0; mf < 4; mf++)
                    mma8(acc[mf][nf], af[mf], bf);
            }
        }
        __syncthreads();
    }

#pragma unroll
    for (int mf = 0; mf < 4; mf++) {
        int r0 = m0 + wm + (mf << 4) + g;
#pragma unroll
        for (int nf = 0; nf < 8; nf++) {
            int c = n0 + wn + (nf << 3) + (tg << 1);
            if (MODE == 0) {
                *(float2*)&C[(size_t)r0 * DIM + c] =
                    make_float2(acc[mf][nf][0], acc[mf][nf][1]);
                *(float2*)&C[(size_t)(r0 + 8) * DIM + c] =
                    make_float2(acc[mf][nf][2], acc[mf][nf][3]);
            } else {
                int h = c >> 6, d = c & 63;
                int bb0 = r0 >> 11, s0 = r0 & 2047;
                int bb1 = (r0 + 8) >> 11, s1 = (r0 + 8) & 2047;
                size_t i0 = (((size_t)(bb0 * HEADS + h) * SEQ + s0) << 6) + d;
                size_t i1 = (((size_t)(bb1 * HEADS + h) * SEQ + s1) << 6) + d;
                *(float2*)&C[i0] = make_float2(tf(acc[mf][nf][0]), tf(acc[mf][nf][1]));
                *(float2*)&C[i1] = make_float2(tf(acc[mf][nf][2]), tf(acc[mf][nf][3]));
            }
        }
    }
}

// fused Q/K/V projection: blockIdx.z selects which projection
__global__ void __launch_bounds__(128, 2) gemm_qkv(
    const float* __restrict__ q, const float* __restrict__ k,
    const float* __restrict__ v,
    const float* __restrict__ WQ, const float* __restrict__ WK,
    const float* __restrict__ WV,
    float* __restrict__ Qh, float* __restrict__ Kh, float* __restrict__ Vh)
{
    const float* A;
    const float* B;
    float* C;
    if (blockIdx.z == 0)      { A = q; B = WQ; C = Qh; }
    else if (blockIdx.z == 1) { A = k; B = WK; C = Kh; }
    else                      { A = v; B = WV; C = Vh; }
    gemm_body<1>(A, B, C, blockIdx.y << 7, blockIdx.x << 7);
}

__global__ void __launch_bounds__(128, 2) gemm_out(
    const float* __restrict__ A, const float* __restrict__ B,
    float* __restrict__ C)
{
    gemm_body<0>(A, B, C, blockIdx.y << 7, blockIdx.x << 7);
}

// ---------------------------------------------------------------------------
// Flash attention, TF32 tensor cores, occupancy-optimized.
// Block = (b, h, 64-query tile), 128 threads = 4 warps, 16 q rows/warp.
// Q fragments in registers (inputs pre-rounded tf32). smem 52.5 KB:
//   Ks[64][68], Vt[64][68] (transposed), Pv[64][68] (V staging, then P),
//   Msh[64]. 3 CTAs/SM -> 12 warps.
// ---------------------------------------------------------------------------
#define FST 68
#define FA_SMEM_FLOATS (3 * 64 * FST + 64)

__global__ void __launch_bounds__(128, 3) flash_tf32(
    const float* __restrict__ Qh, const float* __restrict__ Kh,
    const float* __restrict__ Vh, const float* __restrict__ Mask,
    float* __restrict__ Att)
{
    __shared__ float smf[FA_SMEM_FLOATS];
    float* Ks  = smf;                 // [j][d]
    float* Vt  = smf + 64 * FST;      // [d][j]
    float* Pv  = smf + 2 * 64 * FST;  // V staging [j][d], then P [q][j]
    float* Msh = smf + 3 * 64 * FST;  // [64]

    const int tid = threadIdx.x, lane = tid & 31, w = tid >> 5;
    const int g = lane >> 2, tg = lane & 3;
    const int q0 = w << 4;            // 0,16,32,48
    const int b = blockIdx.z, h = blockIdx.y, qt = blockIdx.x;

    const float* Qg = Qh + ((size_t)(b * HEADS + h) * SEQ + qt * 64) * DEPTH;
    const float* Kg = Kh + (size_t)(b * HEADS + h) * SEQ * DEPTH;
    const float* Vg = Vh + (size_t)(b * HEADS + h) * SEQ * DEPTH;
    const float* Mg = Mask + (size_t)b * SEQ;

    // Q fragments -> registers (pre-rounded tf32; x0.125 exact)
    unsigned qa[8][4];
#pragma unroll
    for (int k0 = 0; k0 < 8; k0++) {
        qa[k0][0] = __float_as_uint(0.125f * Qg[(q0 + g) * DEPTH + (k0 << 3) + tg]);
        qa[k0][1] = __float_as_uint(0.125f * Qg[(q0 + g + 8) * DEPTH + (k0 << 3) + tg]);
        qa[k0][2] = __float_as_uint(0.125f * Qg[(q0 + g) * DEPTH + (k0 << 3) + tg + 4]);
        qa[k0][3] = __float_as_uint(0.125f * Qg[(q0 + g + 8) * DEPTH + (k0 << 3) + tg + 4]);
    }

    float o[8][4];
#pragma unroll
    for (int nf = 0; nf < 8; nf++)
#pragma unroll
        for (int c = 0; c < 4; c++) o[nf][c] = 0.f;
    float mrow[2] = {-1e30f, -1e30f};
    float lrow[2] = {0.f, 0.f};

    for (int kt = 0; kt < SEQ / 64; kt++) {
        __syncthreads();               // (A) prev PV reads (P, Vt) done
        const float* Kgt = Kg + kt * 64 * DEPTH;
        const float* Vgt = Vg + kt * 64 * DEPTH;
#pragma unroll
        for (int it = 0; it < 8; it++) {
            int idx = tid + it * 128;
            int r = idx >> 4, c = (idx & 15) << 2;
            *(float4*)&Ks[r * FST + c] = *(const float4*)(Kgt + r * DEPTH + c);
            *(float4*)&Pv[r * FST + c] = *(const float4*)(Vgt + r * DEPTH + c);
        }
        if (tid < 64) Msh[tid] = Mg[kt * 64 + tid] * 1e9f;
        __syncthreads();               // (B) tiles staged

        // transpose V (Pv) -> Vt[d][j]
        {
            int dd = tid & 63;
            int j0 = (tid >> 6) << 5;
#pragma unroll
            for (int jj = 0; jj < 32; jj += 4) {
                float4 t;
                t.x = Pv[(j0 + jj + 0) * FST + dd];
                t.y = Pv[(j0 + jj + 1) * FST + dd];
                t.z = Pv[(j0 + jj + 2) * FST + dd];
                t.w = Pv[(j0 + jj + 3) * FST + dd];
                *(float4*)&Vt[dd * FST + j0 + jj] = t;
            }
        }

        // S = Q @ K^T
        float s[8][4];
#pragma unroll
        for (int nf = 0; nf < 8; nf++)
#pragma unroll
            for (int c = 0; c < 4; c++) s[nf][c] = 0.f;

#pragma unroll
        for (int k0 = 0; k0 < 8; k0++) {
#pragma unroll
            for (int nf = 0; nf < 8; nf++) {
                unsigned bf[2];
                bf[0] = __float_as_uint(Ks[((nf << 3) + g) * FST + (k0 << 3) + tg]);
                bf[1] = __float_as_uint(Ks[((nf << 3) + g) * FST + (k0 << 3) + tg + 4]);
                mma8(s[nf], qa[k0], bf);
            }
        }

        // mask + online softmax (rows g -> c01, g+8 -> c23)
        float mx[2] = {-1e30f, -1e30f};
#pragma unroll
        for (int nf = 0; nf < 8; nf++) {
            float k0v = Msh[(nf << 3) + (tg << 1)];
            float k1v = Msh[(nf << 3) + (tg << 1) + 1];
            s[nf][0] -= k0v; s[nf][1] -= k1v;
            s[nf][2] -= k0v; s[nf][3] -= k1v;
            mx[0] = fmaxf(mx[0], fmaxf(s[nf][0], s[nf][1]));
            mx[1] = fmaxf(mx[1], fmaxf(s[nf][2], s[nf][3]));
        }
#pragma unroll
        for (int r = 0; r < 2; r++) {
            mx[r] = fmaxf(mx[r], __shfl_xor_sync(0xffffffffu, mx[r], 1));
            mx[r] = fmaxf(mx[r], __shfl_xor_sync(0xffffffffu, mx[r], 2));
        }
        float al[2];
#pragma unroll
        for (int r = 0; r < 2; r++) {
            float mn = fmaxf(mrow[r], mx[r]);
            al[r] = __expf(mrow[r] - mn);
            mrow[r] = mn;
        }
        float sm[2] = {0.f, 0.f};
#pragma unroll
        for (int nf = 0; nf < 8; nf++) {
            s[nf][0] = __expf(s[nf][0] - mrow[0]);
            s[nf][1] = __expf(s[nf][1] - mrow[0]);
            s[nf][2] = __expf(s[nf][2] - mrow[1]);
            s[nf][3] = __expf(s[nf][3] - mrow[1]);
            sm[0] += s[nf][0] + s[nf][1];
            sm[1] += s[nf][2] + s[nf][3];
        }
#pragma unroll
        for (int r = 0; r < 2; r++) {
            sm[r] += __shfl_xor_sync(0xffffffffu, sm[r], 1);
            sm[r] += __shfl_xor_sync(0xffffffffu, sm[r], 2);
            lrow[r] = lrow[r] * al[r] + sm[r];
        }
#pragma unroll
        for (int nf = 0; nf < 8; nf++) {
            o[nf][0] *= al[0]; o[nf][1] *= al[0];
            o[nf][2] *= al[1]; o[nf][3] *= al[1];
        }

        __syncthreads();   // (C) Vt complete; V-staging reads done -> Pv = P

        // P -> smem (warp-private rows)
#pragma unroll
        for (int nf = 0; nf < 8; nf++) {
            *(float2*)&Pv[(q0 + g) * FST + (nf << 3) + (tg << 1)] =
                make_float2(s[nf][0], s[nf][1]);
            *(float2*)&Pv[(q0 + g + 8) * FST + (nf << 3) + (tg << 1)] =
                make_float2(s[nf][2], s[nf][3]);
        }
        __syncwarp();

        // O += P @ V
#pragma unroll
        for (int j0 = 0; j0 < 8; j0++) {
            unsigned pa[4];
            pa[0] = __float_as_uint(Pv[(q0 + g) * FST + (j0 << 3) + tg]);
            pa[1] = __float_as_uint(Pv[(q0 + g + 8) * FST + (j0 << 3) + tg]);
            pa[2] = __float_as_uint(Pv[(q0 + g) * FST + (j0 << 3) + tg + 4]);
            pa[3] = __float_as_uint(Pv[(q0 + g + 8) * FST + (j0 << 3) + tg + 4]);
#pragma unroll
            for (int nf = 0; nf < 8; nf++) {
                unsigned bf[2];
                bf[0] = __float_as_uint(Vt[((nf << 3) + g) * FST + (j0 << 3) + tg]);
                bf[1] = __float_as_uint(Vt[((nf << 3) + g) * FST + (j0 << 3) + tg + 4]);
                mma8(o[nf], pa, bf);
            }
        }
    }

    // normalize + write [B,S,DIM]
    float inv0 = 1.0f / lrow[0], inv1 = 1.0f / lrow[1];
    int r0 = qt * 64 + q0 + g;
    int r1 = r0 + 8;
#pragma unroll
    for (int nf = 0; nf < 8; nf++) {
        int c = h * 64 + (nf << 3) + (tg << 1);
        *(float2*)&Att[(size_t)(b * SEQ + r0) * DIM + c] =
            make_float2(o[nf][0] * inv0, o[nf][1] * inv0);
        *(float2*)&Att[(size_t)(b * SEQ + r1) * DIM + c] =
            make_float2(o[nf][2] * inv1, o[nf][3] * inv1);
    }
}

// ---------------------------------------------------------------------------
extern "C" void kernel_launch(void* const* d_in, const int* in_sizes, int n_in,
                              void* d_out, int out_size)
{
    const float* q    = (const float*)d_in[0];
    const float* k    = (const float*)d_in[1];
    const float* v    = (const float*)d_in[2];
    const float* mask = (const float*)d_in[3];
    const float* WQ   = (const float*)d_in[4];
    const float* WK   = (const float*)d_in[5];
    const float* WV   = (const float*)d_in[6];
    const float* WO   = (const float*)d_in[7];
    float* out = (float*)d_out;

    float *Qh, *Kh, *Vh, *Att;
    cudaGetSymbolAddress((void**)&Qh,  g_Qh);
    cudaGetSymbolAddress((void**)&Kh,  g_Kh);
    cudaGetSymbolAddress((void**)&Vh,  g_Vh);
    cudaGetSymbolAddress((void**)&Att, g_Att);

    dim3 gq(DIM / 128, ROWS / 128, 3);   // (8, 64, 3)
    gemm_qkv<<<gq, 128>>>(q, k, v, WQ, WK, WV, Qh, Kh, Vh);
    flash_tf32<<<dim3(SEQ / 64, HEADS, BATCH), 128>>>(Qh, Kh, Vh, mask, Att);
    dim3 go(DIM / 128, ROWS / 128);      // (8, 64)
    gemm_out<<<go, 128>>>(Att, WO, out);
}

// round 7
// speedup vs baseline: 1.2034x; 1.1446x over previous
#include <cuda_runtime.h>
#include <cstddef>
#include <cstdint>

#define DIM    1024
#define HEADS  16
#define DEPTH  64
#define BATCH  4
#define SEQ    2048
#define ROWS   (BATCH * SEQ)   // 8192

// ---------------- scratch (device globals; no allocation allowed) ----------
__device__ float g_WQt[(size_t)DIM * DIM];    // transposed + tf32-rounded [n][k]
__device__ float g_WKt[(size_t)DIM * DIM];
__device__ float g_WVt[(size_t)DIM * DIM];
__device__ float g_WOt[(size_t)DIM * DIM];
__device__ float g_Qh[(size_t)BATCH * HEADS * SEQ * DEPTH];  // [B,H,S,D]
__device__ float g_Kh[(size_t)BATCH * HEADS * SEQ * DEPTH];
__device__ float g_Vh[(size_t)BATCH * HEADS * SEQ * DEPTH];
__device__ float g_Att[(size_t)ROWS * DIM];                  // [B,S,DIM]

// ---------------- helpers ---------------------------------------------------
__device__ __forceinline__ unsigned f2tf(float x) {
    unsigned u;
    asm("cvt.rna.tf32.f32 %0, %1;" : "=r"(u) : "f"(x));
    return u;
}
__device__ __forceinline__ float tf(float x) { return __uint_as_float(f2tf(x)); }
__device__ __forceinline__ float4 tf4(float4 v) {
    return make_float4(tf(v.x), tf(v.y), tf(v.z), tf(v.w));
}
__device__ __forceinline__ uint32_t smem_u32(const void* p) {
    uint32_t a;
    asm("{ .reg .u64 t; cvta.to.shared.u64 t, %1; cvt.u32.u64 %0, t; }"
        : "=r"(a) : "l"(p));
    return a;
}

// D += A(16x8) * B(8x8), tf32, row.col
__device__ __forceinline__ void mma8(float* d, const unsigned* a, const unsigned* b) {
    asm volatile(
        "mma.sync.aligned.m16n8k8.row.col.f32.tf32.tf32.f32 "
        "{%0,%1,%2,%3},{%4,%5,%6,%7},{%8,%9},{%0,%1,%2,%3};"
        : "+f"(d[0]), "+f"(d[1]), "+f"(d[2]), "+f"(d[3])
        : "r"(a[0]), "r"(a[1]), "r"(a[2]), "r"(a[3]), "r"(b[0]), "r"(b[1]));
}

// ldmatrix x4: four 8x16B tiles; lane i supplies address of row i&7 of tile i>>3
__device__ __forceinline__ void ldsm4(unsigned* r, uint32_t saddr) {
    asm volatile("ldmatrix.sync.aligned.m8n8.x4.shared.b16 {%0,%1,%2,%3}, [%4];"
        : "=r"(r[0]), "=r"(r[1]), "=r"(r[2]), "=r"(r[3]) : "r"(saddr));
}

// ---------------------------------------------------------------------------
// Weight transpose + tf32 rounding prepass: Wt[n][k] = tf(W[k][n])
// ---------------------------------------------------------------------------
__global__ void __launch_bounds__(256) transpose_w(
    const float* __restrict__ WQ, const float* __restrict__ WK,
    const float* __restrict__ WV, const float* __restrict__ WO,
    float* __restrict__ WQt, float* __restrict__ WKt,
    float* __restrict__ WVt, float* __restrict__ WOt)
{
    __shared__ float t[32][33];
    const float* W;
    float* Wt;
    switch (blockIdx.z) {
        case 0: W = WQ; Wt = WQt; break;
        case 1: W = WK; Wt = WKt; break;
        case 2: W = WV; Wt = WVt; break;
        default: W = WO; Wt = WOt; break;
    }
    int tx = threadIdx.x & 31, ty = threadIdx.x >> 5;   // 32 x 8
    int bx = blockIdx.x << 5, by = blockIdx.y << 5;
#pragma unroll
    for (int j = 0; j < 32; j += 8)
        t[ty + j][tx] = W[(size_t)(by + ty + j) * DIM + bx + tx];
    __syncthreads();
#pragma unroll
    for (int j = 0; j < 32; j += 8)
        Wt[(size_t)(bx + ty + j) * DIM + by + tx] = tf(t[tx][ty + j]);
}

// ---------------------------------------------------------------------------
// TF32 GEMM: C = A[M,1024] @ Wt[n][k]^T. Block 128x128, 128 thr = 4 warps,
// warp tile 64x64, k-step 16, register-prefetch double buffering.
// A and B both stored [row][k] with stride 20 floats; fragments via ldmatrix.
// MODE 0: C flat. MODE 1: C scattered to [B,H,S,D], tf32-rounded.
// ---------------------------------------------------------------------------
#define AST 20

template <int MODE>
__device__ __forceinline__ void gemm_body(
    const float* __restrict__ A, const float* __restrict__ Bt,
    float* __restrict__ C, int m0, int n0)
{
    __shared__ float As[128 * AST];   // [m][k0..15]
    __shared__ float Bs[128 * AST];   // [n][k0..15]

    const int tid = threadIdx.x, lane = tid & 31, w = tid >> 5;
    const int g = lane >> 2, tg = lane & 3;
    const int wm = (w & 1) << 6;
    const int wn = (w >> 1) << 6;

    // ldmatrix lane roles
    const int arow  = (lane & 7) + ((lane >> 3) & 1) * 8;  // A tiles: row+8 for t1,t3
    const int akoff = (lane >> 4) * 4;                     // A tiles: k+4 for t2,t3
    const int brow  = (lane & 7) + (lane >> 4) * 8;        // B tiles: n+8 for t2,t3
    const int bkoff = ((lane >> 3) & 1) * 4;               // B tiles: k+4 for t1,t3

    const uint32_t sAs = smem_u32(As);
    const uint32_t sBs = smem_u32(Bs);

    const int r4 = tid >> 2;          // 0..31
    const int c4 = (tid & 3) << 2;    // 0,4,8,12

    float acc[4][8][4];
#pragma unroll
    for (int i = 0; i < 4; i++)
#pragma unroll
        for (int j = 0; j < 8; j++)
#pragma unroll
            for (int c = 0; c < 4; c++) acc[i][j][c] = 0.f;

    float4 pa[4], pb[4];
#pragma unroll
    for (int j = 0; j < 4; j++) {
        pa[j] = *(const float4*)(A  + (size_t)(m0 + r4 + 32 * j) * DIM + c4);
        pb[j] = *(const float4*)(Bt + (size_t)(n0 + r4 + 32 * j) * DIM + c4);
    }

    for (int kk = 0; kk < DIM; kk += 16) {
#pragma unroll
        for (int j = 0; j < 4; j++) {
            *(float4*)&As[(r4 + 32 * j) * AST + c4] = tf4(pa[j]);
            *(float4*)&Bs[(r4 + 32 * j) * AST + c4] = pb[j];   // Wt pre-rounded
        }
        __syncthreads();

        if (kk + 16 < DIM) {
#pragma unroll
            for (int j = 0; j < 4; j++) {
                pa[j] = *(const float4*)(A  + (size_t)(m0 + r4 + 32 * j) * DIM + kk + 16 + c4);
                pb[j] = *(const float4*)(Bt + (size_t)(n0 + r4 + 32 * j) * DIM + kk + 16 + c4);
            }
        }

#pragma unroll
        for (int k0 = 0; k0 < 2; k0++) {
            unsigned af[4][4];
#pragma unroll
            for (int mf = 0; mf < 4; mf++)
                ldsm4(af[mf], sAs + 4u * ((wm + (mf << 4) + arow) * AST + (k0 << 3) + akoff));
            unsigned bf[8][2];
#pragma unroll
            for (int nfp = 0; nfp < 4; nfp++) {
                unsigned t[4];
                ldsm4(t, sBs + 4u * ((wn + (nfp << 4) + brow) * AST + (k0 << 3) + bkoff));
                bf[2 * nfp][0] = t[0];     bf[2 * nfp][1] = t[1];
                bf[2 * nfp + 1][0] = t[2]; bf[2 * nfp + 1][1] = t[3];
            }
#pragma unroll
            for (int nf = 0; nf < 8; nf++)
#pragma unroll
                for (int mf = 0; mf < 4; mf++)
                    mma8(acc[mf][nf], af[mf], bf[nf]);
        }
        __syncthreads();
    }

#pragma unroll
    for (int mf = 0; mf < 4; mf++) {
        int r0 = m0 + wm + (mf << 4) + g;
#pragma unroll
        for (int nf = 0; nf < 8; nf++) {
            int c = n0 + wn + (nf << 3) + (tg << 1);
            if (MODE == 0) {
                *(float2*)&C[(size_t)r0 * DIM + c] =
                    make_float2(acc[mf][nf][0], acc[mf][nf][1]);
                *(float2*)&C[(size_t)(r0 + 8) * DIM + c] =
                    make_float2(acc[mf][nf][2], acc[mf][nf][3]);
            } else {
                int h = c >> 6, d = c & 63;
                int bb0 = r0 >> 11, s0 = r0 & 2047;
                int bb1 = (r0 + 8) >> 11, s1 = (r0 + 8) & 2047;
                size_t i0 = (((size_t)(bb0 * HEADS + h) * SEQ + s0) << 6) + d;
                size_t i1 = (((size_t)(bb1 * HEADS + h) * SEQ + s1) << 6) + d;
                *(float2*)&C[i0] = make_float2(tf(acc[mf][nf][0]), tf(acc[mf][nf][1]));
                *(float2*)&C[i1] = make_float2(tf(acc[mf][nf][2]), tf(acc[mf][nf][3]));
            }
        }
    }
}

__global__ void __launch_bounds__(128, 2) gemm_qkv(
    const float* __restrict__ q, const float* __restrict__ k,
    const float* __restrict__ v,
    const float* __restrict__ WQt, const float* __restrict__ WKt,
    const float* __restrict__ WVt,
    float* __restrict__ Qh, float* __restrict__ Kh, float* __restrict__ Vh)
{
    const float* A;
    const float* B;
    float* C;
    if (blockIdx.z == 0)      { A = q; B = WQt; C = Qh; }
    else if (blockIdx.z == 1) { A = k; B = WKt; C = Kh; }
    else                      { A = v; B = WVt; C = Vh; }
    gemm_body<1>(A, B, C, blockIdx.y << 7, blockIdx.x << 7);
}

__global__ void __launch_bounds__(128, 2) gemm_out(
    const float* __restrict__ A, const float* __restrict__ Bt,
    float* __restrict__ C)
{
    gemm_body<0>(A, Bt, C, blockIdx.y << 7, blockIdx.x << 7);
}

// ---------------------------------------------------------------------------
// Flash attention (R3 structure + ldmatrix fragments).
// Block = (b,h,128-q tile), 128 threads = 4 warps, 32 q rows/warp, K-tiles 64.
// ---------------------------------------------------------------------------
#define FST 68
#define FA_SMEM_FLOATS (128 * FST + 128 * FST + 64 * FST + 64)
#define FA_SMEM_BYTES  (FA_SMEM_FLOATS * 4)

__global__ void __launch_bounds__(128, 2) flash_tf32(
    const float* __restrict__ Qh, const float* __restrict__ Kh,
    const float* __restrict__ Vh, const float* __restrict__ Mask,
    float* __restrict__ Att)
{
    extern __shared__ float smf[];
    float* Qs  = smf;                    // [q][d] 128x68
    float* R1  = smf + 128 * FST;        // K rows 0-63 | V rows 64-127; later P
    float* Vt  = smf + 2 * 128 * FST;    // [d][j] 64x68
    float* Msh = Vt + 64 * FST;

    float* Ksm = R1;
    float* Vsm = R1 + 64 * FST;
    float* Ps  = R1;

    const int tid = threadIdx.x, lane = tid & 31, w = tid >> 5;
    const int g = lane >> 2, tg = lane & 3;
    const int q0 = w << 5;
    const int b = blockIdx.z, h = blockIdx.y, qt = blockIdx.x;

    const int arow  = (lane & 7) + ((lane >> 3) & 1) * 8;
    const int akoff = (lane >> 4) * 4;
    const int brow  = (lane & 7) + (lane >> 4) * 8;
    const int bkoff = ((lane >> 3) & 1) * 4;

    const uint32_t sQs = smem_u32(Qs);
    const uint32_t sKs = smem_u32(Ksm);
    const uint32_t sVt = smem_u32(Vt);
    const uint32_t sPs = sKs;            // P aliases K region

    const float* Qg = Qh + ((size_t)(b * HEADS + h) * SEQ + qt * 128) * DEPTH;
    const float* Kg = Kh + (size_t)(b * HEADS + h) * SEQ * DEPTH;
    const float* Vg = Vh + (size_t)(b * HEADS + h) * SEQ * DEPTH;
    const float* Mg = Mask + (size_t)b * SEQ;

#pragma unroll
    for (int it = 0; it < 16; it++) {
        int idx = tid + it * 128;
        int r = idx >> 4, c = (idx & 15) << 2;
        float4 qv = *(const float4*)(Qg + r * DEPTH + c);
        *(float4*)&Qs[r * FST + c] = make_float4(
            tf(0.125f * qv.x), tf(0.125f * qv.y),
            tf(0.125f * qv.z), tf(0.125f * qv.w));
    }

    float o[2][8][4];
#pragma unroll
    for (int mf = 0; mf < 2; mf++)
#pragma unroll
        for (int nf = 0; nf < 8; nf++)
#pragma unroll
            for (int c = 0; c < 4; c++) o[mf][nf][c] = 0.f;
    float mrow[4] = {-1e30f, -1e30f, -1e30f, -1e30f};
    float lrow[4] = {0.f, 0.f, 0.f, 0.f};

    for (int kt = 0; kt < SEQ / 64; kt++) {
        __syncthreads();                 // (A) prev P/Vt reads done
        const float* Kgt = Kg + kt * 64 * DEPTH;
        const float* Vgt = Vg + kt * 64 * DEPTH;
#pragma unroll
        for (int it = 0; it < 8; it++) {
            int idx = tid + it * 128;
            int r = idx >> 4, c = (idx & 15) << 2;
            *(float4*)&Ksm[r * FST + c] = tf4(*(const float4*)(Kgt + r * DEPTH + c));
            *(float4*)&Vsm[r * FST + c] = tf4(*(const float4*)(Vgt + r * DEPTH + c));
        }
        if (tid < 64) Msh[tid] = Mg[kt * 64 + tid] * 1e9f;
        __syncthreads();                 // (B)

        // transpose V -> Vt[d][j]
        {
            int dd = tid & 63;
            int j0 = (tid >> 6) << 5;
#pragma unroll
            for (int jj = 0; jj < 32; jj += 4) {
                float4 t;
                t.x = Vsm[(j0 + jj + 0) * FST + dd];
                t.y = Vsm[(j0 + jj + 1) * FST + dd];
                t.z = Vsm[(j0 + jj + 2) * FST + dd];
                t.w = Vsm[(j0 + jj + 3) * FST + dd];
                *(float4*)&Vt[dd * FST + j0 + jj] = t;
            }
        }

        // S = Q @ K^T
        float s[2][8][4];
#pragma unroll
        for (int mf = 0; mf < 2; mf++)
#pragma unroll
            for (int nf = 0; nf < 8; nf++)
#pragma unroll
                for (int c = 0; c < 4; c++) s[mf][nf][c] = 0.f;

#pragma unroll
        for (int k0 = 0; k0 < 8; k0++) {
            unsigned qa[2][4];
            ldsm4(qa[0], sQs + 4u * ((q0 + arow) * FST + (k0 << 3) + akoff));
            ldsm4(qa[1], sQs + 4u * ((q0 + 16 + arow) * FST + (k0 << 3) + akoff));
            unsigned bf[8][2];
#pragma unroll
            for (int nfp = 0; nfp < 4; nfp++) {
                unsigned t[4];
                ldsm4(t, sKs + 4u * (((nfp << 4) + brow) * FST + (k0 << 3) + bkoff));
                bf[2 * nfp][0] = t[0];     bf[2 * nfp][1] = t[1];
                bf[2 * nfp + 1][0] = t[2]; bf[2 * nfp + 1][1] = t[3];
            }
#pragma unroll
            for (int nf = 0; nf < 8; nf++) {
                mma8(s[0][nf], qa[0], bf[nf]);
                mma8(s[1][nf], qa[1], bf[nf]);
            }
        }

        // mask + online softmax
        float mx[4] = {-1e30f, -1e30f, -1e30f, -1e30f};
#pragma unroll
        for (int mf = 0; mf < 2; mf++)
#pragma unroll
            for (int nf = 0; nf < 8; nf++) {
                float k0v = Msh[(nf << 3) + (tg << 1)];
                float k1v = Msh[(nf << 3) + (tg << 1) + 1];
                s[mf][nf][0] -= k0v; s[mf][nf][1] -= k1v;
                s[mf][nf][2] -= k0v; s[mf][nf][3] -= k1v;
                mx[mf * 2 + 0] = fmaxf(mx[mf * 2 + 0], fmaxf(s[mf][nf][0], s[mf][nf][1]));
                mx[mf * 2 + 1] = fmaxf(mx[mf * 2 + 1], fmaxf(s[mf][nf][2], s[mf][nf][3]));
            }
#pragma unroll
        for (int r = 0; r < 4; r++) {
            mx[r] = fmaxf(mx[r], __shfl_xor_sync(0xffffffffu, mx[r], 1));
            mx[r] = fmaxf(mx[r], __shfl_xor_sync(0xffffffffu, mx[r], 2));
        }
        float al[4];
#pragma unroll
        for (int r = 0; r < 4; r++) {
            float mn = fmaxf(mrow[r], mx[r]);
            al[r] = __expf(mrow[r] - mn);
            mrow[r] = mn;
        }
        float sm[4] = {0.f, 0.f, 0.f, 0.f};
#pragma unroll
        for (int mf = 0; mf < 2; mf++)
#pragma unroll
            for (int nf = 0; nf < 8; nf++) {
                s[mf][nf][0] = __expf(s[mf][nf][0] - mrow[mf * 2 + 0]);
                s[mf][nf][1] = __expf(s[mf][nf][1] - mrow[mf * 2 + 0]);
                s[mf][nf][2] = __expf(s[mf][nf][2] - mrow[mf * 2 + 1]);
                s[mf][nf][3] = __expf(s[mf][nf][3] - mrow[mf * 2 + 1]);
                sm[mf * 2 + 0] += s[mf][nf][0] + s[mf][nf][1];
                sm[mf * 2 + 1] += s[mf][nf][2] + s[mf][nf][3];
            }
#pragma unroll
        for (int r = 0; r < 4; r++) {
            sm[r] += __shfl_xor_sync(0xffffffffu, sm[r], 1);
            sm[r] += __shfl_xor_sync(0xffffffffu, sm[r], 2);
            lrow[r] = lrow[r] * al[r] + sm[r];
        }
#pragma unroll
        for (int mf = 0; mf < 2; mf++)
#pragma unroll
            for (int nf = 0; nf < 8; nf++) {
                o[mf][nf][0] *= al[mf * 2 + 0]; o[mf][nf][1] *= al[mf * 2 + 0];
                o[mf][nf][2] *= al[mf * 2 + 1]; o[mf][nf][3] *= al[mf * 2 + 1];
            }

        __syncthreads();   // (C) Vt done; K reads done -> region becomes P

        // P -> smem (warp-private rows)
#pragma unroll
        for (int mf = 0; mf < 2; mf++) {
            int m = q0 + (mf << 4);
#pragma unroll
            for (int nf = 0; nf < 8; nf++) {
                *(float2*)&Ps[(m + g) * FST + (nf << 3) + (tg << 1)] =
                    make_float2(s[mf][nf][0], s[mf][nf][1]);
                *(float2*)&Ps[(m + g + 8) * FST + (nf << 3) + (tg << 1)] =
                    make_float2(s[mf][nf][2], s[mf][nf][3]);
            }
        }
        __syncwarp();

        // O += P @ V
#pragma unroll
        for (int j0 = 0; j0 < 8; j0++) {
            unsigned pa[2][4];
            ldsm4(pa[0], sPs + 4u * ((q0 + arow) * FST + (j0 << 3) + akoff));
            ldsm4(pa[1], sPs + 4u * ((q0 + 16 + arow) * FST + (j0 << 3) + akoff));
            unsigned bf[8][2];
#pragma unroll
            for (int nfp = 0; nfp < 4; nfp++) {
                unsigned t[4];
                ldsm4(t, sVt + 4u * (((nfp << 4) + brow) * FST + (j0 << 3) + bkoff));
                bf[2 * nfp][0] = t[0];     bf[2 * nfp][1] = t[1];
                bf[2 * nfp + 1][0] = t[2]; bf[2 * nfp + 1][1] = t[3];
            }
#pragma unroll
            for (int nf = 0; nf < 8; nf++) {
                mma8(o[0][nf], pa[0], bf[nf]);
                mma8(o[1][nf], pa[1], bf[nf]);
            }
        }
    }

    // normalize + write [B,S,DIM]
#pragma unroll
    for (int mf = 0; mf < 2; mf++) {
        float inv0 = 1.0f / lrow[mf * 2 + 0];
        float inv1 = 1.0f / lrow[mf * 2 + 1];
        int r0 = qt * 128 + q0 + (mf << 4) + g;
        int r1 = r0 + 8;
#pragma unroll
        for (int nf = 0; nf < 8; nf++) {
            int c = h * 64 + (nf << 3) + (tg << 1);
            *(float2*)&Att[(size_t)(b * SEQ + r0) * DIM + c] =
                make_float2(o[mf][nf][0] * inv0, o[mf][nf][1] * inv0);
            *(float2*)&Att[(size_t)(b * SEQ + r1) * DIM + c] =
                make_float2(o[mf][nf][2] * inv1, o[mf][nf][3] * inv1);
        }
    }
}

// ---------------------------------------------------------------------------
extern "C" void kernel_launch(void* const* d_in, const int* in_sizes, int n_in,
                              void* d_out, int out_size)
{
    const float* q    = (const float*)d_in[0];
    const float* k    = (const float*)d_in[1];
    const float* v    = (const float*)d_in[2];
    const float* mask = (const float*)d_in[3];
    const float* WQ   = (const float*)d_in[4];
    const float* WK   = (const float*)d_in[5];
    const float* WV   = (const float*)d_in[6];
    const float* WO   = (const float*)d_in[7];
    float* out = (float*)d_out;

    float *WQt, *WKt, *WVt, *WOt, *Qh, *Kh, *Vh, *Att;
    cudaGetSymbolAddress((void**)&WQt, g_WQt);
    cudaGetSymbolAddress((void**)&WKt, g_WKt);
    cudaGetSymbolAddress((void**)&WVt, g_WVt);
    cudaGetSymbolAddress((void**)&WOt, g_WOt);
    cudaGetSymbolAddress((void**)&Qh,  g_Qh);
    cudaGetSymbolAddress((void**)&Kh,  g_Kh);
    cudaGetSymbolAddress((void**)&Vh,  g_Vh);
    cudaGetSymbolAddress((void**)&Att, g_Att);

    cudaFuncSetAttribute(flash_tf32,
                         cudaFuncAttributeMaxDynamicSharedMemorySize,
                         FA_SMEM_BYTES);

    transpose_w<<<dim3(32, 32, 4), 256>>>(WQ, WK, WV, WO, WQt, WKt, WVt, WOt);

    dim3 gq(DIM / 128, ROWS / 128, 3);   // (8, 64, 3)
    gemm_qkv<<<gq, 128>>>(q, k, v, WQt, WKt, WVt, Qh, Kh, Vh);

    flash_tf32<<<dim3(SEQ / 128, HEADS, BATCH), 128, FA_SMEM_BYTES>>>(
        Qh, Kh, Vh, mask, Att);

    dim3 go(DIM / 128, ROWS / 128);      // (8, 64)
    gemm_out<<<go, 128>>>(Att, WOt, out);
}

// round 8
// speedup vs baseline: 1.3417x; 1.1149x over previous
#include <cuda_runtime.h>
#include <cstddef>
#include <cstdint>

#define DIM    1024
#define HEADS  16
#define DEPTH  64
#define BATCH  4
#define SEQ    2048
#define ROWS   (BATCH * SEQ)   // 8192

// ---------------- scratch (device globals; no allocation allowed) ----------
__device__ float g_rq[(size_t)ROWS * DIM];    // rna-rounded inputs
__device__ float g_rk[(size_t)ROWS * DIM];
__device__ float g_rv[(size_t)ROWS * DIM];
__device__ float g_WQt[(size_t)DIM * DIM];    // transposed + rounded [n][k]
__device__ float g_WKt[(size_t)DIM * DIM];
__device__ float g_WVt[(size_t)DIM * DIM];
__device__ float g_WOt[(size_t)DIM * DIM];
__device__ float g_Qh[(size_t)BATCH * HEADS * SEQ * DEPTH];  // [B,H,S,D] rounded
__device__ float g_Kh[(size_t)BATCH * HEADS * SEQ * DEPTH];
__device__ float g_Vh[(size_t)BATCH * HEADS * SEQ * DEPTH];
__device__ float g_Att[(size_t)ROWS * DIM];                  // [B,S,DIM] rounded

// ---------------- helpers ---------------------------------------------------
__device__ __forceinline__ unsigned f2tf(float x) {
    unsigned u;
    asm("cvt.rna.tf32.f32 %0, %1;" : "=r"(u) : "f"(x));
    return u;
}
__device__ __forceinline__ float tf(float x) { return __uint_as_float(f2tf(x)); }
__device__ __forceinline__ float4 tf4(float4 v) {
    return make_float4(tf(v.x), tf(v.y), tf(v.z), tf(v.w));
}
__device__ __forceinline__ uint32_t smem_u32(const void* p) {
    uint32_t a;
    asm("{ .reg .u64 t; cvta.to.shared.u64 t, %1; cvt.u32.u64 %0, t; }"
        : "=r"(a) : "l"(p));
    return a;
}
__device__ __forceinline__ void cp16(void* dst, const void* src) {
    unsigned d = (unsigned)__cvta_generic_to_shared(dst);
    asm volatile("cp.async.cg.shared.global [%0], [%1], 16;" :: "r"(d), "l"(src));
}
#define CP_COMMIT() asm volatile("cp.async.commit_group;")

// D += A(16x8) * B(8x8), tf32, row.col
__device__ __forceinline__ void mma8(float* d, const unsigned* a, const unsigned* b) {
    asm volatile(
        "mma.sync.aligned.m16n8k8.row.col.f32.tf32.tf32.f32 "
        "{%0,%1,%2,%3},{%4,%5,%6,%7},{%8,%9},{%0,%1,%2,%3};"
        : "+f"(d[0]), "+f"(d[1]), "+f"(d[2]), "+f"(d[3])
        : "r"(a[0]), "r"(a[1]), "r"(a[2]), "r"(a[3]), "r"(b[0]), "r"(b[1]));
}
__device__ __forceinline__ void ldsm4(unsigned* r, uint32_t saddr) {
    asm volatile("ldmatrix.sync.aligned.m8n8.x4.shared.b16 {%0,%1,%2,%3}, [%4];"
        : "=r"(r[0]), "=r"(r[1]), "=r"(r[2]), "=r"(r[3]) : "r"(saddr));
}

// ---------------------------------------------------------------------------
// Prepass: rna-round q/k/v
// ---------------------------------------------------------------------------
__global__ void __launch_bounds__(256) round3(
    const float* __restrict__ q, const float* __restrict__ k,
    const float* __restrict__ v,
    float* __restrict__ rq, float* __restrict__ rk, float* __restrict__ rv)
{
    const float* src = blockIdx.z == 0 ? q : (blockIdx.z == 1 ? k : v);
    float* dst = blockIdx.z == 0 ? rq : (blockIdx.z == 1 ? rk : rv);
    size_t i = ((size_t)blockIdx.x * 256 + threadIdx.x) * 4;
    *(float4*)(dst + i) = tf4(*(const float4*)(src + i));
}

// Weight transpose + rounding: Wt[n][k] = tf(W[k][n])
__global__ void __launch_bounds__(256) transpose_w(
    const float* __restrict__ WQ, const float* __restrict__ WK,
    const float* __restrict__ WV, const float* __restrict__ WO,
    float* __restrict__ WQt, float* __restrict__ WKt,
    float* __restrict__ WVt, float* __restrict__ WOt)
{
    __shared__ float t[32][33];
    const float* W;
    float* Wt;
    switch (blockIdx.z) {
        case 0: W = WQ; Wt = WQt; break;
        case 1: W = WK; Wt = WKt; break;
        case 2: W = WV; Wt = WVt; break;
        default: W = WO; Wt = WOt; break;
    }
    int tx = threadIdx.x & 31, ty = threadIdx.x >> 5;
    int bx = blockIdx.x << 5, by = blockIdx.y << 5;
#pragma unroll
    for (int j = 0; j < 32; j += 8)
        t[ty + j][tx] = W[(size_t)(by + ty + j) * DIM + bx + tx];
    __syncthreads();
#pragma unroll
    for (int j = 0; j < 32; j += 8)
        Wt[(size_t)(bx + ty + j) * DIM + by + tx] = tf(t[tx][ty + j]);
}

// ---------------------------------------------------------------------------
// TF32 GEMM: C = A[M,1024] @ Bt[n][k]^T. Inputs pre-rounded.
// Block 128x128, 128 thr = 4 warps (2x2), warp tile 64x64, k-step 32,
// 3-stage cp.async, SW128-swizzled 128B rows, fragments via ldmatrix.
// MODE 0: C flat. MODE 1: C scattered to [B,H,S,D], tf32-rounded.
// ---------------------------------------------------------------------------
#define GST 32768                 // bytes per stage: A 16KB + B 16KB
#define GEMM_SMEM (3 * GST)

template <int MODE>
__device__ __forceinline__ void gemm_body(
    const float* __restrict__ A, const float* __restrict__ Bt,
    float* __restrict__ C, int m0, int n0)
{
    extern __shared__ char gsm[];

    const int tid = threadIdx.x, lane = tid & 31, w = tid >> 5;
    const int g = lane >> 2, tg = lane & 3;
    const int wm = (w & 1) << 6;
    const int wn = (w >> 1) << 6;

    // ldmatrix lane roles (b16 m8n8: lane supplies row of its tile)
    const int arow = (lane & 7) + ((lane >> 3) & 1) * 8;   // tiles 0/2: +0, 1/3: +8
    const int achk = (lane >> 4);                          // k-chunk +1 for t2,t3
    const int brow = (lane & 7) + (lane >> 4) * 8;
    const int bchk = ((lane >> 3) & 1);

    const int cr = tid >> 3;          // copy row 0..15 (x8 = 128 rows)
    const int cc = tid & 7;           // copy chunk 0..7

    float acc[4][8][4];
#pragma unroll
    for (int i = 0; i < 4; i++)
#pragma unroll
        for (int j = 0; j < 8; j++)
#pragma unroll
            for (int c = 0; c < 4; c++) acc[i][j][c] = 0.f;

    auto stage_copy = [&](int s, int p) {
        char* st = gsm + p * GST;
        const float* Ag = A  + (size_t)m0 * DIM + s * 32;
        const float* Bg = Bt + (size_t)n0 * DIM + s * 32;
#pragma unroll
        for (int t = 0; t < 8; t++) {
            int r = cr + t * 16;
            uint32_t off = r * 128 + ((cc ^ (r & 7)) << 4);
            cp16(st + off,         Ag + (size_t)r * DIM + (cc << 2));
            cp16(st + 16384 + off, Bg + (size_t)r * DIM + (cc << 2));
        }
        CP_COMMIT();
    };

    stage_copy(0, 0);
    stage_copy(1, 1);
    stage_copy(2, 2);

    const int NS = DIM / 32;   // 32
    for (int s = 0; s < NS; s++) {
        int p = s % 3;
        asm volatile("cp.async.wait_group 2;" ::: "memory");
        __syncthreads();

        const uint32_t sA = smem_u32(gsm + p * GST);
        const uint32_t sB = sA + 16384;

#pragma unroll
        for (int k0 = 0; k0 < 4; k0++) {
            unsigned af[4][4];
#pragma unroll
            for (int mf = 0; mf < 4; mf++) {
                int r = wm + (mf << 4) + arow;
                int ch = (k0 << 1) + achk;
                ldsm4(af[mf], sA + r * 128 + ((ch ^ (r & 7)) << 4));
            }
            unsigned bf[8][2];
#pragma unroll
            for (int nfp = 0; nfp < 4; nfp++) {
                int r = wn + (nfp << 4) + brow;
                int ch = (k0 << 1) + bchk;
                unsigned t[4];
                ldsm4(t, sB + r * 128 + ((ch ^ (r & 7)) << 4));
                bf[2 * nfp][0] = t[0];     bf[2 * nfp][1] = t[1];
                bf[2 * nfp + 1][0] = t[2]; bf[2 * nfp + 1][1] = t[3];
            }
#pragma unroll
            for (int nf = 0; nf < 8; nf++)
#pragma unroll
                for (int mf = 0; mf < 4; mf++)
                    mma8(acc[mf][nf], af[mf], bf[nf]);
        }
        __syncthreads();

        if (s + 3 < NS) stage_copy(s + 3, p);
        else            CP_COMMIT();      // keep group accounting exact
    }

#pragma unroll
    for (int mf = 0; mf < 4; mf++) {
        int r0 = m0 + wm + (mf << 4) + g;
#pragma unroll
        for (int nf = 0; nf < 8; nf++) {
            int c = n0 + wn + (nf << 3) + (tg << 1);
            if (MODE == 0) {
                *(float2*)&C[(size_t)r0 * DIM + c] =
                    make_float2(acc[mf][nf][0], acc[mf][nf][1]);
                *(float2*)&C[(size_t)(r0 + 8) * DIM + c] =
                    make_float2(acc[mf][nf][2], acc[mf][nf][3]);
            } else {
                int h = c >> 6, d = c & 63;
                int bb0 = r0 >> 11, s0 = r0 & 2047;
                int bb1 = (r0 + 8) >> 11, s1 = (r0 + 8) & 2047;
                size_t i0 = (((size_t)(bb0 * HEADS + h) * SEQ + s0) << 6) + d;
                size_t i1 = (((size_t)(bb1 * HEADS + h) * SEQ + s1) << 6) + d;
                *(float2*)&C[i0] = make_float2(tf(acc[mf][nf][0]), tf(acc[mf][nf][1]));
                *(float2*)&C[i1] = make_float2(tf(acc[mf][nf][2]), tf(acc[mf][nf][3]));
            }
        }
    }
}

__global__ void __launch_bounds__(128, 2) gemm_qkv(
    const float* __restrict__ rq, const float* __restrict__ rk,
    const float* __restrict__ rv,
    const float* __restrict__ WQt, const float* __restrict__ WKt,
    const float* __restrict__ WVt,
    float* __restrict__ Qh, float* __restrict__ Kh, float* __restrict__ Vh)
{
    const float* A;
    const float* B;
    float* C;
    if (blockIdx.z == 0)      { A = rq; B = WQt; C = Qh; }
    else if (blockIdx.z == 1) { A = rk; B = WKt; C = Kh; }
    else                      { A = rv; B = WVt; C = Vh; }
    gemm_body<1>(A, B, C, blockIdx.y << 7, blockIdx.x << 7);
}

__global__ void __launch_bounds__(128, 2) gemm_out(
    const float* __restrict__ A, const float* __restrict__ Bt,
    float* __restrict__ C)
{
    gemm_body<0>(A, Bt, C, blockIdx.y << 7, blockIdx.x << 7);
}

// ---------------------------------------------------------------------------
// Flash attention (R7 + cvt-free cp.async staging, tf-rounded output).
// Block = (b,h,128-q tile), 128 threads = 4 warps, 32 q rows/warp, K-tiles 64.
// ---------------------------------------------------------------------------
#define FST 68
#define FA_SMEM_FLOATS (128 * FST + 128 * FST + 64 * FST + 64)
#define FA_SMEM_BYTES  (FA_SMEM_FLOATS * 4)

__global__ void __launch_bounds__(128, 2) flash_tf32(
    const float* __restrict__ Qh, const float* __restrict__ Kh,
    const float* __restrict__ Vh, const float* __restrict__ Mask,
    float* __restrict__ Att)
{
    extern __shared__ float smf[];
    float* Qs  = smf;                    // [q][d] 128x68
    float* R1  = smf + 128 * FST;        // K rows 0-63 | V rows 64-127; later P
    float* Vt  = smf + 2 * 128 * FST;    // [d][j] 64x68
    float* Msh = Vt + 64 * FST;

    float* Ksm = R1;
    float* Vsm = R1 + 64 * FST;
    float* Ps  = R1;

    const int tid = threadIdx.x, lane = tid & 31, w = tid >> 5;
    const int g = lane >> 2, tg = lane & 3;
    const int q0 = w << 5;
    const int b = blockIdx.z, h = blockIdx.y, qt = blockIdx.x;

    const int arow  = (lane & 7) + ((lane >> 3) & 1) * 8;
    const int akoff = (lane >> 4) * 4;
    const int brow  = (lane & 7) + (lane >> 4) * 8;
    const int bkoff = ((lane >> 3) & 1) * 4;

    const uint32_t sQs = smem_u32(Qs);
    const uint32_t sKs = smem_u32(Ksm);
    const uint32_t sVt = smem_u32(Vt);
    const uint32_t sPs = sKs;

    const float* Qg = Qh + ((size_t)(b * HEADS + h) * SEQ + qt * 128) * DEPTH;
    const float* Kg = Kh + (size_t)(b * HEADS + h) * SEQ * DEPTH;
    const float* Vg = Vh + (size_t)(b * HEADS + h) * SEQ * DEPTH;
    const float* Mg = Mask + (size_t)b * SEQ;

    // Q tile: pre-rounded tf32; x0.125 exact (power of two)
#pragma unroll
    for (int it = 0; it < 16; it++) {
        int idx = tid + it * 128;
        int r = idx >> 4, c = (idx & 15) << 2;
        float4 qv = *(const float4*)(Qg + r * DEPTH + c);
        *(float4*)&Qs[r * FST + c] = make_float4(
            0.125f * qv.x, 0.125f * qv.y, 0.125f * qv.z, 0.125f * qv.w);
    }

    float o[2][8][4];
#pragma unroll
    for (int mf = 0; mf < 2; mf++)
#pragma unroll
        for (int nf = 0; nf < 8; nf++)
#pragma unroll
            for (int c = 0; c < 4; c++) o[mf][nf][c] = 0.f;
    float mrow[4] = {-1e30f, -1e30f, -1e30f, -1e30f};
    float lrow[4] = {0.f, 0.f, 0.f, 0.f};

    for (int kt = 0; kt < SEQ / 64; kt++) {
        __syncthreads();                 // (A) prev P/Vt reads done
        const float* Kgt = Kg + kt * 64 * DEPTH;
        const float* Vgt = Vg + kt * 64 * DEPTH;
#pragma unroll
        for (int it = 0; it < 8; it++) {
            int idx = tid + it * 128;
            int r = idx >> 4, c = (idx & 15) << 2;
            cp16(&Ksm[r * FST + c], Kgt + r * DEPTH + c);
            cp16(&Vsm[r * FST + c], Vgt + r * DEPTH + c);
        }
        CP_COMMIT();
        if (tid < 64) Msh[tid] = Mg[kt * 64 + tid] * 1e9f;
        asm volatile("cp.async.wait_group 0;" ::: "memory");
        __syncthreads();                 // (B)

        // transpose V -> Vt[d][j]
        {
            int dd = tid & 63;
            int j0 = (tid >> 6) << 5;
#pragma unroll
            for (int jj = 0; jj < 32; jj += 4) {
                float4 t;
                t.x = Vsm[(j0 + jj + 0) * FST + dd];
                t.y = Vsm[(j0 + jj + 1) * FST + dd];
                t.z = Vsm[(j0 + jj + 2) * FST + dd];
                t.w = Vsm[(j0 + jj + 3) * FST + dd];
                *(float4*)&Vt[dd * FST + j0 + jj] = t;
            }
        }

        // S = Q @ K^T
        float s[2][8][4];
#pragma unroll
        for (int mf = 0; mf < 2; mf++)
#pragma unroll
            for (int nf = 0; nf < 8; nf++)
#pragma unroll
                for (int c = 0; c < 4; c++) s[mf][nf][c] = 0.f;

#pragma unroll
        for (int k0 = 0; k0 < 8; k0++) {
            unsigned qa[2][4];
            ldsm4(qa[0], sQs + 4u * ((q0 + arow) * FST + (k0 << 3) + akoff));
            ldsm4(qa[1], sQs + 4u * ((q0 + 16 + arow) * FST + (k0 << 3) + akoff));
            unsigned bf[8][2];
#pragma unroll
            for (int nfp = 0; nfp < 4; nfp++) {
                unsigned t[4];
                ldsm4(t, sKs + 4u * (((nfp << 4) + brow) * FST + (k0 << 3) + bkoff));
                bf[2 * nfp][0] = t[0];     bf[2 * nfp][1] = t[1];
                bf[2 * nfp + 1][0] = t[2]; bf[2 * nfp + 1][1] = t[3];
            }
#pragma unroll
            for (int nf = 0; nf < 8; nf++) {
                mma8(s[0][nf], qa[0], bf[nf]);
                mma8(s[1][nf], qa[1], bf[nf]);
            }
        }

        // mask + online softmax
        float mx[4] = {-1e30f, -1e30f, -1e30f, -1e30f};
#pragma unroll
        for (int mf = 0; mf < 2; mf++)
#pragma unroll
            for (int nf = 0; nf < 8; nf++) {
                float k0v = Msh[(nf << 3) + (tg << 1)];
                float k1v = Msh[(nf << 3) + (tg << 1) + 1];
                s[mf][nf][0] -= k0v; s[mf][nf][1] -= k1v;
                s[mf][nf][2] -= k0v; s[mf][nf][3] -= k1v;
                mx[mf * 2 + 0] = fmaxf(mx[mf * 2 + 0], fmaxf(s[mf][nf][0], s[mf][nf][1]));
                mx[mf * 2 + 1] = fmaxf(mx[mf * 2 + 1], fmaxf(s[mf][nf][2], s[mf][nf][3]));
            }
#pragma unroll
        for (int r = 0; r < 4; r++) {
            mx[r] = fmaxf(mx[r], __shfl_xor_sync(0xffffffffu, mx[r], 1));
            mx[r] = fmaxf(mx[r], __shfl_xor_sync(0xffffffffu, mx[r], 2));
        }
        float al[4];
#pragma unroll
        for (int r = 0; r < 4; r++) {
            float mn = fmaxf(mrow[r], mx[r]);
            al[r] = __expf(mrow[r] - mn);
            mrow[r] = mn;
        }
        float sm[4] = {0.f, 0.f, 0.f, 0.f};
#pragma unroll
        for (int mf = 0; mf < 2; mf++)
#pragma unroll
            for (int nf = 0; nf < 8; nf++) {
                s[mf][nf][0] = __expf(s[mf][nf][0] - mrow[mf * 2 + 0]);
                s[mf][nf][1] = __expf(s[mf][nf][1] - mrow[mf * 2 + 0]);
                s[mf][nf][2] = __expf(s[mf][nf][2] - mrow[mf * 2 + 1]);
                s[mf][nf][3] = __expf(s[mf][nf][3] - mrow[mf * 2 + 1]);
                sm[mf * 2 + 0] += s[mf][nf][0] + s[mf][nf][1];
                sm[mf * 2 + 1] += s[mf][nf][2] + s[mf][nf][3];
            }
#pragma unroll
        for (int r = 0; r < 4; r++) {
            sm[r] += __shfl_xor_sync(0xffffffffu, sm[r], 1);
            sm[r] += __shfl_xor_sync(0xffffffffu, sm[r], 2);
            lrow[r] = lrow[r] * al[r] + sm[r];
        }
#pragma unroll
        for (int mf = 0; mf < 2; mf++)
#pragma unroll
            for (int nf = 0; nf < 8; nf++) {
                o[mf][nf][0] *= al[mf * 2 + 0]; o[mf][nf][1] *= al[mf * 2 + 0];
                o[mf][nf][2] *= al[mf * 2 + 1]; o[mf][nf][3] *= al[mf * 2 + 1];
            }

        __syncthreads();   // (C) Vt done; K reads done -> region becomes P

#pragma unroll
        for (int mf = 0; mf < 2; mf++) {
            int m = q0 + (mf << 4);
#pragma unroll
            for (int nf = 0; nf < 8; nf++) {
                *(float2*)&Ps[(m + g) * FST + (nf << 3) + (tg << 1)] =
                    make_float2(s[mf][nf][0], s[mf][nf][1]);
                *(float2*)&Ps[(m + g + 8) * FST + (nf << 3) + (tg << 1)] =
                    make_float2(s[mf][nf][2], s[mf][nf][3]);
            }
        }
        __syncwarp();

        // O += P @ V
#pragma unroll
        for (int j0 = 0; j0 < 8; j0++) {
            unsigned pa[2][4];
            ldsm4(pa[0], sPs + 4u * ((q0 + arow) * FST + (j0 << 3) + akoff));
            ldsm4(pa[1], sPs + 4u * ((q0 + 16 + arow) * FST + (j0 << 3) + akoff));
            unsigned bf[8][2];
#pragma unroll
            for (int nfp = 0; nfp < 4; nfp++) {
                unsigned t[4];
                ldsm4(t, sVt + 4u * (((nfp << 4) + brow) * FST + (j0 << 3) + bkoff));
                bf[2 * nfp][0] = t[0];     bf[2 * nfp][1] = t[1];
                bf[2 * nfp + 1][0] = t[2]; bf[2 * nfp + 1][1] = t[3];
            }
#pragma unroll
            for (int nf = 0; nf < 8; nf++) {
                mma8(o[0][nf], pa[0], bf[nf]);
                mma8(o[1][nf], pa[1], bf[nf]);
            }
        }
    }

    // normalize + write tf32-rounded [B,S,DIM]
#pragma unroll
    for (int mf = 0; mf < 2; mf++) {
        float inv0 = 1.0f / lrow[mf * 2 + 0];
        float inv1 = 1.0f / lrow[mf * 2 + 1];
        int r0 = qt * 128 + q0 + (mf << 4) + g;
        int r1 = r0 + 8;
#pragma unroll
        for (int nf = 0; nf < 8; nf++) {
            int c = h * 64 + (nf << 3) + (tg << 1);
            *(float2*)&Att[(size_t)(b * SEQ + r0) * DIM + c] =
                make_float2(tf(o[mf][nf][0] * inv0), tf(o[mf][nf][1] * inv0));
            *(float2*)&Att[(size_t)(b * SEQ + r1) * DIM + c] =
                make_float2(tf(o[mf][nf][2] * inv1), tf(o[mf][nf][3] * inv1));
        }
    }
}

// ---------------------------------------------------------------------------
extern "C" void kernel_launch(void* const* d_in, const int* in_sizes, int n_in,
                              void* d_out, int out_size)
{
    const float* q    = (const float*)d_in[0];
    const float* k    = (const float*)d_in[1];
    const float* v    = (const float*)d_in[2];
    const float* mask = (const float*)d_in[3];
    const float* WQ   = (const float*)d_in[4];
    const float* WK   = (const float*)d_in[5];
    const float* WV   = (const float*)d_in[6];
    const float* WO   = (const float*)d_in[7];
    float* out = (float*)d_out;

    float *rq, *rk, *rv, *WQt, *WKt, *WVt, *WOt, *Qh, *Kh, *Vh, *Att;
    cudaGetSymbolAddress((void**)&rq,  g_rq);
    cudaGetSymbolAddress((void**)&rk,  g_rk);
    cudaGetSymbolAddress((void**)&rv,  g_rv);
    cudaGetSymbolAddress((void**)&WQt, g_WQt);
    cudaGetSymbolAddress((void**)&WKt, g_WKt);
    cudaGetSymbolAddress((void**)&WVt, g_WVt);
    cudaGetSymbolAddress((void**)&WOt, g_WOt);
    cudaGetSymbolAddress((void**)&Qh,  g_Qh);
    cudaGetSymbolAddress((void**)&Kh,  g_Kh);
    cudaGetSymbolAddress((void**)&Vh,  g_Vh);
    cudaGetSymbolAddress((void**)&Att, g_Att);

    cudaFuncSetAttribute(gemm_qkv,
                         cudaFuncAttributeMaxDynamicSharedMemorySize, GEMM_SMEM);
    cudaFuncSetAttribute(gemm_out,
                         cudaFuncAttributeMaxDynamicSharedMemorySize, GEMM_SMEM);
    cudaFuncSetAttribute(flash_tf32,
                         cudaFuncAttributeMaxDynamicSharedMemorySize, FA_SMEM_BYTES);

    round3<<<dim3(ROWS * DIM / 1024, 1, 3), 256>>>(q, k, v, rq, rk, rv);
    transpose_w<<<dim3(32, 32, 4), 256>>>(WQ, WK, WV, WO, WQt, WKt, WVt, WOt);

    dim3 gq(DIM / 128, ROWS / 128, 3);   // (8, 64, 3)
    gemm_qkv<<<gq, 128, GEMM_SMEM>>>(rq, rk, rv, WQt, WKt, WVt, Qh, Kh, Vh);

    flash_tf32<<<dim3(SEQ / 128, HEADS, BATCH), 128, FA_SMEM_BYTES>>>(
        Qh, Kh, Vh, mask, Att);

    dim3 go(DIM / 128, ROWS / 128);      // (8, 64)
    gemm_out<<<go, 128, GEMM_SMEM>>>(Att, WOt, out);
}